// round 8
// baseline (speedup 1.0000x reference)
#include <cuda_runtime.h>
#include <cuda_bf16.h>

// Problem shape: pred [N=262144, C=1000] fp32, labels [N] int32, out: 1 fp32 scalar.
#define C_CLASSES 1000
#define V4_PER_ROW 250          // 1000 / 4 floats per float4
#define WARPS_PER_BLOCK 8
#define BLOCK_THREADS 256
#define NUM_SMS 148
#define BLOCKS_PER_SM 8
#define NUM_BLOCKS (NUM_SMS * BLOCKS_PER_SM)   // 1184 persistent blocks
#define MAX_PARTIALS 2048

__device__ float        g_partials[MAX_PARTIALS];
__device__ unsigned int g_arrive;   // zero-init at load; last block resets it each launch

// Pinned config (measured): occ=8 blocks/SM, 32 regs, 64 warps/SM, persistent
// grid, label pipeline one row ahead. This round: sweep loads use __ldcg
// (L1-bypass, normal L2) instead of __ldcs (evict-first L1+L2): L1 fills of
// single-use data are pure overhead, while L2 normal-evict protects the
// xl-prefetched line and row-boundary lines shared across 8-row groups.
__global__ __launch_bounds__(BLOCK_THREADS, BLOCKS_PER_SM)
void loss_fused(const float* __restrict__ pred,
                const int* __restrict__ labels,
                float* __restrict__ out,
                int N, float invN) {
    const int lane    = threadIdx.x & 31;
    const int wid     = threadIdx.x >> 5;
    const int gwarp   = blockIdx.x * WARPS_PER_BLOCK + wid;
    const int wstride = NUM_BLOCKS * WARPS_PER_BLOCK;      // 9472

    float acc = 0.0f;   // lane-0 accumulator of per-row loss terms (fixed order)

    // Prime the label pipeline: label for the FIRST row, loaded before the loop.
    int lbl = 0;
    if (gwarp < N) {
        lbl = __ldg(labels + gwarp);
        lbl = min(max(lbl, 0), C_CLASSES - 1);
    }

    for (int row = gwarp; row < N; row += wstride) {
        const float4* rp = reinterpret_cast<const float4*>(pred + (size_t)row * C_CLASSES);

        // Label logit for THIS row: lbl already resident -> issues immediately,
        // latency fully overlapped by the sweep. Also prefetches that line into
        // L2 for the sweep loads below.
        const float xl = __ldg(pred + (size_t)row * C_CLASSES + lbl);

        // ---- Load batch: iters 0..6 always in range (lane+6*32=223<250),
        // only iter 7 predicated. __ldcg: L2-only, single-use streaming data.
        float4 v[8];
        #pragma unroll
        for (int i = 0; i < 7; i++) {
            v[i] = __ldcg(rp + (lane + i * 32));
        }
        {
            const int j = lane + 7 * 32;
            v[7] = make_float4(-1e30f, -1e30f, -1e30f, -1e30f);  // exp->0, max-neutral
            if (j < V4_PER_ROW) v[7] = __ldcg(rp + j);
        }

        // Prefetch NEXT row's label (latency hidden under this row's math).
        const int nrow = row + wstride;
        int lbln = 0;
        if (nrow < N) {
            lbln = __ldg(labels + nrow);
            lbln = min(max(lbln, 0), C_CLASSES - 1);
        }

        // ---- Math on registers ----
        float m1 = -1e30f, m2 = -1e30f, s = 0.0f;
        #pragma unroll
        for (int i = 0; i < 8; i++) {
            const float4 w = v[i];
            s += __expf(w.x) + __expf(w.y) + __expf(w.z) + __expf(w.w);
            m2 = fmaxf(m2, fminf(m1, w.x)); m1 = fmaxf(m1, w.x);
            m2 = fmaxf(m2, fminf(m1, w.y)); m1 = fmaxf(m1, w.y);
            m2 = fmaxf(m2, fminf(m1, w.z)); m1 = fmaxf(m1, w.z);
            m2 = fmaxf(m2, fminf(m1, w.w)); m1 = fmaxf(m1, w.w);
        }

        // ---- Warp butterfly: sum s, merge top-2 sets ----
        #pragma unroll
        for (int o = 16; o > 0; o >>= 1) {
            float om1 = __shfl_xor_sync(0xffffffffu, m1, o);
            float om2 = __shfl_xor_sync(0xffffffffu, m2, o);
            s        += __shfl_xor_sync(0xffffffffu, s,  o);
            m2 = fmaxf(fminf(m1, om1), fmaxf(m2, om2));
            m1 = fmaxf(m1, om1);
        }

        if (lane == 0) {
            const float inv_s = 1.0f / s;
            const float p     = __expf(xl) * inv_s;                  // softmax prob of label
            const float diff  = (__expf(m1) - __expf(m2)) * inv_s;   // top1 - top2 prob
            const float y     = 3.0f * diff;
            const float logp  = xl - __logf(s);                      // log softmax of label
            float w = 1.0f;
            if (y > 0.01f) w = __powf(1.0f - p, y);                  // else exponent := 0 -> w=1
            acc -= w * logp;
        }

        lbl = lbln;   // advance the label pipeline
    }

    // ---- One block epilogue per persistent block ----
    __shared__ float sh[WARPS_PER_BLOCK];
    __shared__ bool  s_islast;
    if (lane == 0) sh[wid] = acc;
    __syncthreads();
    if (threadIdx.x == 0) {
        float bs = 0.0f;
        #pragma unroll
        for (int i = 0; i < WARPS_PER_BLOCK; i++) bs += sh[i];
        g_partials[blockIdx.x] = bs;
        __threadfence();                                   // publish partial before arrival
        unsigned int t = atomicAdd(&g_arrive, 1u);
        s_islast = (t == (unsigned int)(NUM_BLOCKS - 1));
    }
    __syncthreads();

    // ---- Last block: final deterministic reduction over 1184 partials ----
    if (s_islast) {
        __threadfence();                                   // acquire all partials
        float s = 0.0f;
        for (int i = threadIdx.x; i < NUM_BLOCKS; i += BLOCK_THREADS) s += g_partials[i];

        __shared__ float shr[BLOCK_THREADS / 32];
        #pragma unroll
        for (int o = 16; o > 0; o >>= 1) s += __shfl_xor_sync(0xffffffffu, s, o);
        if (lane == 0) shr[wid] = s;
        __syncthreads();
        if (threadIdx.x < 32) {
            float vv = (threadIdx.x < BLOCK_THREADS / 32) ? shr[threadIdx.x] : 0.0f;
            #pragma unroll
            for (int o = 4; o > 0; o >>= 1) vv += __shfl_xor_sync(0xffffffffu, vv, o);
            if (threadIdx.x == 0) {
                out[0] = vv * invN;
                g_arrive = 0;                              // reset for next graph replay
            }
        }
    }
}

extern "C" void kernel_launch(void* const* d_in, const int* in_sizes, int n_in,
                              void* d_out, int out_size) {
    const float* pred   = (const float*)d_in[0];
    const int*   labels = (const int*)d_in[1];
    const int N = in_sizes[1];                 // labels element count = row count

    loss_fused<<<NUM_BLOCKS, BLOCK_THREADS>>>(pred, labels, (float*)d_out,
                                              N, 1.0f / (float)N);
}

// round 9
// speedup vs baseline: 1.0328x; 1.0328x over previous
#include <cuda_runtime.h>
#include <cuda_bf16.h>

// Problem shape: pred [N=262144, C=1000] fp32, labels [N] int32, out: 1 fp32 scalar.
#define C_CLASSES 1000
#define V4_PER_ROW 250          // 1000 / 4 floats per float4
#define WARPS_PER_BLOCK 8
#define BLOCK_THREADS 256
#define NUM_SMS 148
#define BLOCKS_PER_SM 8
#define NUM_BLOCKS (NUM_SMS * BLOCKS_PER_SM)   // 1184 persistent blocks
#define MAX_PARTIALS 2048

__device__ float        g_partials[MAX_PARTIALS];
__device__ unsigned int g_arrive;   // zero-init at load; last block resets it each launch

// FINAL measured configuration (best: 152.1 us, DRAM 85.3%):
//  - occ=8 blocks/SM, 32 regs, 64 warps/SM (R4: occupancy is load-bearing;
//    forcing 64 regs/occ-4 regressed to 201 us)
//  - persistent grid, 8 consecutive rows per block-iteration (R6)
//  - label + label-logit pipelined one row ahead (R7)
//  - __ldcs on the sweep (R8: __ldcg is NOT better — L1% is queue traversal,
//    not fills; L2 evict-first on single-use stream is the right policy)
__global__ __launch_bounds__(BLOCK_THREADS, BLOCKS_PER_SM)
void loss_fused(const float* __restrict__ pred,
                const int* __restrict__ labels,
                float* __restrict__ out,
                int N, float invN) {
    const int lane    = threadIdx.x & 31;
    const int wid     = threadIdx.x >> 5;
    const int gwarp   = blockIdx.x * WARPS_PER_BLOCK + wid;
    const int wstride = NUM_BLOCKS * WARPS_PER_BLOCK;      // 9472

    float acc = 0.0f;   // lane-0 accumulator of per-row loss terms (fixed order)

    // Prime the label pipeline: label for the FIRST row, loaded before the loop.
    int lbl = 0;
    if (gwarp < N) {
        lbl = __ldg(labels + gwarp);
        lbl = min(max(lbl, 0), C_CLASSES - 1);
    }

    for (int row = gwarp; row < N; row += wstride) {
        const float4* rp = reinterpret_cast<const float4*>(pred + (size_t)row * C_CLASSES);

        // Label logit for THIS row: lbl already resident -> issues immediately,
        // latency fully overlapped by the sweep.
        const float xl = __ldg(pred + (size_t)row * C_CLASSES + lbl);

        // ---- Load batch: iters 0..6 always in range (lane+6*32=223<250),
        // only iter 7 predicated. __ldcs: single-use streaming data.
        float4 v[8];
        #pragma unroll
        for (int i = 0; i < 7; i++) {
            v[i] = __ldcs(rp + (lane + i * 32));
        }
        {
            const int j = lane + 7 * 32;
            v[7] = make_float4(-1e30f, -1e30f, -1e30f, -1e30f);  // exp->0, max-neutral
            if (j < V4_PER_ROW) v[7] = __ldcs(rp + j);
        }

        // Prefetch NEXT row's label (latency hidden under this row's math).
        const int nrow = row + wstride;
        int lbln = 0;
        if (nrow < N) {
            lbln = __ldg(labels + nrow);
            lbln = min(max(lbln, 0), C_CLASSES - 1);
        }

        // ---- Math on registers ----
        float m1 = -1e30f, m2 = -1e30f, s = 0.0f;
        #pragma unroll
        for (int i = 0; i < 8; i++) {
            const float4 w = v[i];
            s += __expf(w.x) + __expf(w.y) + __expf(w.z) + __expf(w.w);
            m2 = fmaxf(m2, fminf(m1, w.x)); m1 = fmaxf(m1, w.x);
            m2 = fmaxf(m2, fminf(m1, w.y)); m1 = fmaxf(m1, w.y);
            m2 = fmaxf(m2, fminf(m1, w.z)); m1 = fmaxf(m1, w.z);
            m2 = fmaxf(m2, fminf(m1, w.w)); m1 = fmaxf(m1, w.w);
        }

        // ---- Warp butterfly: sum s, merge top-2 sets ----
        #pragma unroll
        for (int o = 16; o > 0; o >>= 1) {
            float om1 = __shfl_xor_sync(0xffffffffu, m1, o);
            float om2 = __shfl_xor_sync(0xffffffffu, m2, o);
            s        += __shfl_xor_sync(0xffffffffu, s,  o);
            m2 = fmaxf(fminf(m1, om1), fmaxf(m2, om2));
            m1 = fmaxf(m1, om1);
        }

        if (lane == 0) {
            const float inv_s = 1.0f / s;
            const float p     = __expf(xl) * inv_s;                  // softmax prob of label
            const float diff  = (__expf(m1) - __expf(m2)) * inv_s;   // top1 - top2 prob
            const float y     = 3.0f * diff;
            const float logp  = xl - __logf(s);                      // log softmax of label
            float w = 1.0f;
            if (y > 0.01f) w = __powf(1.0f - p, y);                  // else exponent := 0 -> w=1
            acc -= w * logp;
        }

        lbl = lbln;   // advance the label pipeline
    }

    // ---- One block epilogue per persistent block ----
    __shared__ float sh[WARPS_PER_BLOCK];
    __shared__ bool  s_islast;
    if (lane == 0) sh[wid] = acc;
    __syncthreads();
    if (threadIdx.x == 0) {
        float bs = 0.0f;
        #pragma unroll
        for (int i = 0; i < WARPS_PER_BLOCK; i++) bs += sh[i];
        g_partials[blockIdx.x] = bs;
        __threadfence();                                   // publish partial before arrival
        unsigned int t = atomicAdd(&g_arrive, 1u);
        s_islast = (t == (unsigned int)(NUM_BLOCKS - 1));
    }
    __syncthreads();

    // ---- Last block: final deterministic reduction over 1184 partials ----
    if (s_islast) {
        __threadfence();                                   // acquire all partials
        float s = 0.0f;
        for (int i = threadIdx.x; i < NUM_BLOCKS; i += BLOCK_THREADS) s += g_partials[i];

        __shared__ float shr[BLOCK_THREADS / 32];
        #pragma unroll
        for (int o = 16; o > 0; o >>= 1) s += __shfl_xor_sync(0xffffffffu, s, o);
        if (lane == 0) shr[wid] = s;
        __syncthreads();
        if (threadIdx.x < 32) {
            float vv = (threadIdx.x < BLOCK_THREADS / 32) ? shr[threadIdx.x] : 0.0f;
            #pragma unroll
            for (int o = 4; o > 0; o >>= 1) vv += __shfl_xor_sync(0xffffffffu, vv, o);
            if (threadIdx.x == 0) {
                out[0] = vv * invN;
                g_arrive = 0;                              // reset for next graph replay
            }
        }
    }
}

extern "C" void kernel_launch(void* const* d_in, const int* in_sizes, int n_in,
                              void* d_out, int out_size) {
    const float* pred   = (const float*)d_in[0];
    const int*   labels = (const int*)d_in[1];
    const int N = in_sizes[1];                 // labels element count = row count

    loss_fused<<<NUM_BLOCKS, BLOCK_THREADS>>>(pred, labels, (float*)d_out,
                                              N, 1.0f / (float)N);
}